// round 10
// baseline (speedup 1.0000x reference)
#include <cuda_runtime.h>
#include <cstdint>

// SpikeFP64ExtractLow6 — persistent warp-ballot kernel, single-wave grid.
//   e = int from x[1..11] (x[1] MSB), s = (e + 1025) & 2047
//   v = (s<=5) ? ((0b1 m0..m5) >> (6-s)) & 63 : 0,  m_i = x[12+i]
// m5 never used; m4 = x[16] only when s == 5 (p~1/2048) -> rare ballot-guarded
// load. Reads touch bytes 0..63/row; DRAM moves the full 128B line regardless
// (measured R1/R3/R5/R6) -> traffic floor ~304 MB, achieved at ~6.2 TB/s.
// This round: grid-stride persistent loop, grid = 148 SM x 8 blocks = one wave,
// eliminating ~5.6 wave transitions' worth of DRAM-queue drain.

constexpr int NUM_SMS    = 148;
constexpr int BLOCKS_SM  = 8;
constexpr int GRID_BLKS  = NUM_SMS * BLOCKS_SM;   // 1184
constexpr int BLOCK_THREADS = 256;

__global__ __launch_bounds__(BLOCK_THREADS) void spike_extract_kernel(
        const float* __restrict__ x,
        float* __restrict__ out,
        int n) {
    const int lane    = threadIdx.x & 31;
    const int warp0   = (blockIdx.x * BLOCK_THREADS + threadIdx.x) >> 5;
    const int nwarps  = (GRID_BLKS * BLOCK_THREADS) >> 5;   // 9472
    const int ntiles  = (n + 31) >> 5;                       // 32-row tiles

    for (int tile = warp0; tile < ntiles; tile += nwarps) {
        const int row0 = tile * 32;

        if (row0 + 32 <= n) {
            // ---- bulk load: 16 LDG in flight per warp ----
            // lanes 0-15: col=lane of rows row0+i; lanes 16-31: col=lane-16 of rows row0+16+i
            const float* base = x + (size_t)(row0 + ((lane >= 16) ? 16 : 0)) * 64
                                  + (lane & 15);
            float vals[16];
            #pragma unroll
            for (int i = 0; i < 16; i++)
                vals[i] = __ldcg(base + (size_t)i * 64);

            unsigned myb = 0;
            #pragma unroll
            for (int i = 0; i < 16; i++) {
                unsigned b = __ballot_sync(0xFFFFFFFFu, vals[i] != 0.0f);
                if ((lane & 15) == i)
                    myb = (lane < 16) ? (b & 0xFFFFu) : (b >> 16);
            }
            // lane l owns row row0 + l (lo halves for lanes 0-15, hi for 16-31)

            // ---- decode ----
            unsigned rb = __brev(myb);
            unsigned s  = (((rb >> 20) & 0x7FFu) + 1025u) & 2047u;
            unsigned Mp = 16u | ((rb >> 16) & 15u);          // 1 m0 m1 m2 m3
            unsigned v  = (s <= 4u) ? (Mp >> ((4u - s) & 31u)) : 0u;

            // rare s==5 fix-up: warp-uniform branch (~1.5% of tiles)
            if (__ballot_sync(0xFFFFFFFFu, s == 5u)) {
                if (s == 5u) {
                    unsigned m4 = (x[(size_t)(row0 + lane) * 64 + 16] != 0.0f);
                    v = ((Mp << 1) | m4) & 63u;
                }
            }

            // ---- coalesced store: 32 rows * 6 floats = 48 float4 ----
            float4* obase = reinterpret_cast<float4*>(out + (size_t)row0 * 6);
            {
                float4 o;
                #pragma unroll
                for (int j = 0; j < 4; j++) {
                    int f  = lane * 4 + j;              // 0..127
                    int sr = f / 6;                     // source row 0..21
                    int bp = 5 - (f - sr * 6);
                    unsigned vv = __shfl_sync(0xFFFFFFFFu, v, sr);
                    (&o.x)[j] = (float)((vv >> bp) & 1u);
                }
                obase[lane] = o;
            }
            {
                float4 o;
                #pragma unroll
                for (int j = 0; j < 4; j++) {
                    int f  = 128 + lane * 4 + j;
                    int sr = f / 6;
                    int bp = 5 - (f - sr * 6);
                    int src = sr < 32 ? sr : 31;        // clamp; high lanes unused
                    unsigned vv = __shfl_sync(0xFFFFFFFFu, v, src);
                    (&o.x)[j] = (float)((vv >> bp) & 1u);
                }
                if (lane < 16) obase[32 + lane] = o;
            }
        } else {
            // ---- tail tile (n % 32 rows; never hit for n = 2e6) ----
            int r = row0 + lane;
            if (r < n) {
                const float* fr = x + (size_t)r * 64;
                unsigned e = 0;
                #pragma unroll
                for (int k = 1; k <= 11; k++)
                    e = (e << 1) | (fr[k] != 0.0f ? 1u : 0u);
                unsigned s = (e + 1025u) & 2047u;
                unsigned M = 1u;
                #pragma unroll
                for (int i = 0; i < 6; i++)
                    M = (M << 1) | (fr[12 + i] != 0.0f ? 1u : 0u);
                unsigned v = (s <= 5u) ? ((M >> ((6u - s) & 31u)) & 63u) : 0u;
                float* o = out + (size_t)r * 6;
                #pragma unroll
                for (int j = 0; j < 6; j++)
                    o[j] = (float)((v >> (5 - j)) & 1u);
            }
        }
    }
}

extern "C" void kernel_launch(void* const* d_in, const int* in_sizes, int n_in,
                              void* d_out, int out_size) {
    const float* x = (const float*)d_in[0];
    float* out = (float*)d_out;
    int n = in_sizes[0] / 64;                 // 2,000,000 rows
    spike_extract_kernel<<<GRID_BLKS, BLOCK_THREADS>>>(x, out, n);
}

// round 11
// speedup vs baseline: 1.0477x; 1.0477x over previous
#include <cuda_runtime.h>
#include <cstdint>

// SpikeFP64ExtractLow6 — FINAL: warp-ballot, 32 rows/warp (R9 config).
//   e = int from x[1..11] (x[1] MSB), s = (e + 1025) & 2047
//   v = (s<=5) ? ((0b1 m0..m5) >> (6-s)) & 63 : 0,  m_i = x[12+i]
// Facts established over R1-R10:
//   * m5 never used; m4 = x[16] only when s == 5 (p~1/2048) -> rare
//     ballot-guarded load.
//   * DRAM moves the full 128B line per row regardless of sectors requested
//     (R1/R3/R5 traffic identical) -> traffic floor ~288-304 MB, achieved.
//   * Memory system pins at 6.0-6.2 TB/s for this mixed stream; L1-wavefront
//     reduction (R3), occupancy (R9), and wave elimination (R10) all flat ->
//     this is the device ceiling for the workload. regs=28, occ~80%.

__global__ __launch_bounds__(256) void spike_extract_kernel(
        const float* __restrict__ x,
        float* __restrict__ out,
        int n) {
    const int warpId = (blockIdx.x * blockDim.x + threadIdx.x) >> 5;
    const int lane   = threadIdx.x & 31;
    const int row0   = warpId * 32;
    if (row0 >= n) return;                      // whole-warp exit only

    if (row0 + 32 <= n) {
        // ---- bulk load: 16 LDG in flight per warp, L1-bypass ----
        // lanes 0-15: col=lane of rows row0+i; lanes 16-31: col=lane-16 of rows row0+16+i
        const float* base = x + (size_t)(row0 + ((lane >= 16) ? 16 : 0)) * 64
                              + (lane & 15);
        float vals[16];
        #pragma unroll
        for (int i = 0; i < 16; i++)
            vals[i] = __ldcg(base + (size_t)i * 64);

        unsigned myb = 0;
        #pragma unroll
        for (int i = 0; i < 16; i++) {
            unsigned b = __ballot_sync(0xFFFFFFFFu, vals[i] != 0.0f);
            if ((lane & 15) == i)
                myb = (lane < 16) ? (b & 0xFFFFu) : (b >> 16);
        }
        // lane l owns row row0 + l (lo halves for lanes 0-15, hi for 16-31)

        // ---- decode ----
        unsigned rb = __brev(myb);
        unsigned s  = (((rb >> 20) & 0x7FFu) + 1025u) & 2047u;
        unsigned Mp = 16u | ((rb >> 16) & 15u);          // 1 m0 m1 m2 m3
        unsigned v  = (s <= 4u) ? (Mp >> ((4u - s) & 31u)) : 0u;

        // rare s==5 fix-up: warp-uniform branch (~1.5% of warps)
        if (__ballot_sync(0xFFFFFFFFu, s == 5u)) {
            if (s == 5u) {
                unsigned m4 = (x[(size_t)(row0 + lane) * 64 + 16] != 0.0f);
                v = ((Mp << 1) | m4) & 63u;
            }
        }

        // ---- coalesced store: 32 rows * 6 floats = 48 float4 ----
        float4* obase = reinterpret_cast<float4*>(out + (size_t)row0 * 6);
        {
            float4 o;
            #pragma unroll
            for (int j = 0; j < 4; j++) {
                int f  = lane * 4 + j;              // 0..127
                int sr = f / 6;                     // source row 0..21
                int bp = 5 - (f - sr * 6);
                unsigned vv = __shfl_sync(0xFFFFFFFFu, v, sr);
                (&o.x)[j] = (float)((vv >> bp) & 1u);
            }
            obase[lane] = o;
        }
        {
            float4 o;
            #pragma unroll
            for (int j = 0; j < 4; j++) {
                int f  = 128 + lane * 4 + j;
                int sr = f / 6;
                int bp = 5 - (f - sr * 6);
                int src = sr < 32 ? sr : 31;        // clamp; high lanes unused
                unsigned vv = __shfl_sync(0xFFFFFFFFu, v, src);
                (&o.x)[j] = (float)((vv >> bp) & 1u);
            }
            if (lane < 16) obase[32 + lane] = o;
        }
    } else {
        // ---- tail path (n % 32 rows; never hit for n = 2e6) ----
        int r = row0 + lane;
        if (r < n) {
            const float* fr = x + (size_t)r * 64;
            unsigned e = 0;
            #pragma unroll
            for (int k = 1; k <= 11; k++)
                e = (e << 1) | (fr[k] != 0.0f ? 1u : 0u);
            unsigned s = (e + 1025u) & 2047u;
            unsigned M = 1u;
            #pragma unroll
            for (int i = 0; i < 6; i++)
                M = (M << 1) | (fr[12 + i] != 0.0f ? 1u : 0u);
            unsigned v = (s <= 5u) ? ((M >> ((6u - s) & 31u)) & 63u) : 0u;
            float* o = out + (size_t)r * 6;
            #pragma unroll
            for (int j = 0; j < 6; j++)
                o[j] = (float)((v >> (5 - j)) & 1u);
        }
    }
}

extern "C" void kernel_launch(void* const* d_in, const int* in_sizes, int n_in,
                              void* d_out, int out_size) {
    const float* x = (const float*)d_in[0];
    float* out = (float*)d_out;
    int n = in_sizes[0] / 64;                 // 2,000,000 rows
    int nwarps = (n + 31) / 32;
    long long nthreads = (long long)nwarps * 32;
    int grid = (int)((nthreads + 255) / 256);
    spike_extract_kernel<<<grid, 256>>>(x, out, n);
}